// round 1
// baseline (speedup 1.0000x reference)
#include <cuda_runtime.h>
#include <math.h>

// Problem constants
#define Bsz   1024
#define Tlen  80
#define Dd    512
#define Cc    78      // VOCAB+1
#define Mrows (Bsz*Tlen)   // 81920
#define BLANKI 77
#define PRED  30
#define LOGITS_ELEMS ((size_t)Mrows * Cc)  // 6,389,760

// argmax path scratch (static device global — no runtime alloc)
__device__ int g_best[Mrows];

// ---------------------------------------------------------------------------
// Fused GEMM (fp32, exact) + softmax + per-row argmax.
// Tile: 128 rows x 80 cols (78 real + 2 pad) per CTA, BK=16, double-buffered.
// 256 threads, each computes an 8x5 register tile.
// ---------------------------------------------------------------------------
__global__ __launch_bounds__(256)
void gemm_softmax_kernel(const float* __restrict__ feat,
                         const float* __restrict__ Wm,
                         const float* __restrict__ bias,
                         float* __restrict__ out)
{
    __shared__ union {
        struct {
            float feat[2][16][128];  // [stage][k][row]  (transposed for float4 row reads)
            float w[2][16][80];      // [stage][k][col]
        } ld;
        float outs[128][81];         // epilogue staging (81 = pad for bank-conflict-free col scans)
    } sm;
    __shared__ float bias_s[80];
    __shared__ float rmax[128];
    __shared__ float rinv[128];

    const int t  = threadIdx.x;
    const int tx = t & 15;        // col group: cols tx*5 .. tx*5+4
    const int ty = t >> 4;        // row group: rows ty*8 .. ty*8+7
    const int m0 = blockIdx.x * 128;

    if (t < 80) bias_s[t] = (t < Cc) ? bias[t] : 0.0f;

    float acc[8][5];
#pragma unroll
    for (int i = 0; i < 8; i++)
#pragma unroll
        for (int u = 0; u < 5; u++) acc[i][u] = 0.0f;

    // ---- load chunk 0 into stage 0 ----
    {
#pragma unroll
        for (int i = 0; i < 2; i++) {
            int lid = t + 256 * i;
            int r = lid >> 2, kq = lid & 3;
            float4 v = *reinterpret_cast<const float4*>(feat + (size_t)(m0 + r) * Dd + kq * 4);
            sm.ld.feat[0][kq * 4 + 0][r] = v.x;
            sm.ld.feat[0][kq * 4 + 1][r] = v.y;
            sm.ld.feat[0][kq * 4 + 2][r] = v.z;
            sm.ld.feat[0][kq * 4 + 3][r] = v.w;
        }
#pragma unroll
        for (int i = 0; i < 5; i++) {
            int lid = t + 256 * i;
            int k = lid / 80, cc2 = lid - k * 80;
            sm.ld.w[0][k][cc2] = (cc2 < Cc) ? Wm[(size_t)k * Cc + cc2] : 0.0f;
        }
    }
    __syncthreads();

    // ---- main loop over 32 K-chunks, single-sync double buffer ----
    for (int ch = 0; ch < 32; ++ch) {
        const int s = ch & 1;
        float4 pf[2];
        float  pw[5];
        if (ch < 31) {
            const int kb = (ch + 1) * 16;
#pragma unroll
            for (int i = 0; i < 2; i++) {
                int lid = t + 256 * i;
                int r = lid >> 2, kq = lid & 3;
                pf[i] = *reinterpret_cast<const float4*>(feat + (size_t)(m0 + r) * Dd + kb + kq * 4);
            }
#pragma unroll
            for (int i = 0; i < 5; i++) {
                int lid = t + 256 * i;
                int k = lid / 80, cc2 = lid - k * 80;
                pw[i] = (cc2 < Cc) ? Wm[(size_t)(kb + k) * Cc + cc2] : 0.0f;
            }
        }

#pragma unroll
        for (int kk = 0; kk < 16; kk++) {
            float4 a0 = *reinterpret_cast<const float4*>(&sm.ld.feat[s][kk][ty * 8]);
            float4 a1 = *reinterpret_cast<const float4*>(&sm.ld.feat[s][kk][ty * 8 + 4]);
            float bz[5];
#pragma unroll
            for (int u = 0; u < 5; u++) bz[u] = sm.ld.w[s][kk][tx * 5 + u];
            float av[8] = {a0.x, a0.y, a0.z, a0.w, a1.x, a1.y, a1.z, a1.w};
#pragma unroll
            for (int i = 0; i < 8; i++)
#pragma unroll
                for (int u = 0; u < 5; u++)
                    acc[i][u] += av[i] * bz[u];
        }

        if (ch < 31) {
            const int s2 = (ch + 1) & 1;
#pragma unroll
            for (int i = 0; i < 2; i++) {
                int lid = t + 256 * i;
                int r = lid >> 2, kq = lid & 3;
                sm.ld.feat[s2][kq * 4 + 0][r] = pf[i].x;
                sm.ld.feat[s2][kq * 4 + 1][r] = pf[i].y;
                sm.ld.feat[s2][kq * 4 + 2][r] = pf[i].z;
                sm.ld.feat[s2][kq * 4 + 3][r] = pf[i].w;
            }
#pragma unroll
            for (int i = 0; i < 5; i++) {
                int lid = t + 256 * i;
                int k = lid / 80, cc2 = lid - k * 80;
                sm.ld.w[s2][k][cc2] = pw[i];
            }
        }
        __syncthreads();
    }

    // ---- stage accumulators in smem (aliases load buffers; all consumers synced) ----
#pragma unroll
    for (int i = 0; i < 8; i++)
#pragma unroll
        for (int u = 0; u < 5; u++)
            sm.outs[ty * 8 + i][tx * 5 + u] = acc[i][u];
    __syncthreads();

    // ---- per-row max / argmax / exp-sum ----
    if (t < 128) {
        const int r = t;
        float mx = -1e30f;
        int   am = 0;
        for (int c2 = 0; c2 < Cc; c2++) {
            float v = sm.outs[r][c2] + bias_s[c2];
            if (v > mx) { mx = v; am = c2; }
        }
        float ssum = 0.0f;
        for (int c2 = 0; c2 < Cc; c2++)
            ssum += expf(sm.outs[r][c2] + bias_s[c2] - mx);
        rmax[r] = mx;
        rinv[r] = 1.0f / ssum;
        g_best[m0 + r] = am;
    }
    __syncthreads();

    // ---- coalesced softmax writes ----
    for (int idx = t; idx < 128 * Cc; idx += 256) {
        int r = idx / Cc, c2 = idx - r * Cc;
        out[(size_t)(m0 + r) * Cc + c2] =
            expf(sm.outs[r][c2] + bias_s[c2] - rmax[r]) * rinv[r];
    }
}

// ---------------------------------------------------------------------------
// CTC greedy collapse: merge repeats, drop blank(77), pad to 30 with -1.
// Labels written value-cast to float after the logits region.
// ---------------------------------------------------------------------------
__global__ void decode_kernel(float* __restrict__ out, size_t out_elems)
{
    int b = blockIdx.x * blockDim.x + threadIdx.x;
    if (b >= Bsz) return;
    size_t base = LOGITS_ELEMS + (size_t)b * PRED;
    if (base + PRED > out_elems) return;  // layout safety guard
    float* lab = out + base;
#pragma unroll
    for (int i = 0; i < PRED; i++) lab[i] = -1.0f;

    const int* bb = g_best + (size_t)b * Tlen;
    int prev = -1, cnt = 0;
    for (int tt = 0; tt < Tlen; tt++) {
        int v = bb[tt];
        if (v != BLANKI && v != prev && cnt < PRED) {
            lab[cnt] = (float)v;
            cnt++;
        }
        prev = v;
    }
}

extern "C" void kernel_launch(void* const* d_in, const int* in_sizes, int n_in,
                              void* d_out, int out_size)
{
    const float* feat = (const float*)d_in[0];  // [1024,80,512]
    const float* Wm   = (const float*)d_in[1];  // [512,78]
    const float* bias = (const float*)d_in[2];  // [78]
    // d_in[3] = y (unused), d_in[4] = times (constant 80)
    float* out = (float*)d_out;

    gemm_softmax_kernel<<<Mrows / 128, 256>>>(feat, Wm, bias, out);
    decode_kernel<<<4, 256>>>(out, (size_t)out_size);
}